// round 2
// baseline (speedup 1.0000x reference)
#include <cuda_runtime.h>

#define MAXN 100000
#define MAXE 1600000
#define HID 64

// ---- scratch (device globals; no allocation allowed) ----
__device__ __align__(256) float g_t[MAXN * HID];     // h @ W
__device__ __align__(256) float g_agg[MAXN * HID];   // aggregated messages
__device__ __align__(256) float g_dis[MAXN];         // deg^{-1/2}
__device__ __align__(256) float g_norm[MAXE];        // per-edge norm
__device__ __align__(256) int   g_deg[MAXN];

// ---------------- small prep kernels ----------------
__global__ void zero_deg_kernel(int n) {
    int i = blockIdx.x * blockDim.x + threadIdx.x;
    if (i < n) g_deg[i] = 0;
}

__global__ void count_deg_kernel(const int* __restrict__ dst, int E) {
    int e = blockIdx.x * blockDim.x + threadIdx.x;
    if (e < E) atomicAdd(&g_deg[dst[e]], 1);
}

__global__ void compute_dis_kernel(int n) {
    int i = blockIdx.x * blockDim.x + threadIdx.x;
    if (i < n) g_dis[i] = rsqrtf((float)(g_deg[i] + 1));  // +1 self loop
}

__global__ void compute_norm_kernel(const int* __restrict__ src,
                                    const int* __restrict__ dst, int E) {
    int e = blockIdx.x * blockDim.x + threadIdx.x;
    if (e < E) g_norm[e] = g_dis[src[e]] * g_dis[dst[e]];
}

// ---------------- GEMM: out[N,64] = f(in)[N,K] @ W[K,64] ----------------
// f = relu for layers 2..4 (applied on tile load). Uses fma.rn.f32x2 packed FMA.
__device__ __forceinline__ unsigned long long fma2(unsigned long long a,
                                                   unsigned long long b,
                                                   unsigned long long c) {
    unsigned long long d;
    asm("fma.rn.f32x2 %0, %1, %2, %3;" : "=l"(d) : "l"(a), "l"(b), "l"(c));
    return d;
}

template <int K, bool RELU>
__global__ void gemm64_kernel(const float* __restrict__ in,
                              const float* __restrict__ W,
                              float* __restrict__ out, int n) {
    extern __shared__ float sm[];
    float* Ws  = sm;                // K*64 floats
    float* inS = sm + K * 64;       // 32 rows, stride K+4 (bank-conflict pad)
    const int tid = threadIdx.x;    // 128 threads
    const int STR = K + 4;

    // load W (contiguous)
    {
        const float4* W4 = (const float4*)W;
        float4* Ws4 = (float4*)Ws;
        for (int i = tid; i < K * 16; i += 128) Ws4[i] = W4[i];
    }
    // load 32-node input tile (rows contiguous in gmem)
    int base = blockIdx.x * 32;
    {
        const int K4 = K / 4;
        const float4* in4 = (const float4*)(in + (size_t)base * K);
        for (int i = tid; i < 32 * K4; i += 128) {
            int node = i / K4, k4 = i % K4;
            float4 v;
            if (base + node < n) v = in4[i];
            else v = make_float4(0.f, 0.f, 0.f, 0.f);
            if (RELU) {
                v.x = fmaxf(v.x, 0.f); v.y = fmaxf(v.y, 0.f);
                v.z = fmaxf(v.z, 0.f); v.w = fmaxf(v.w, 0.f);
            }
            ((float4*)(inS + node * STR))[k4] = v;
        }
    }
    __syncthreads();

    const int tx = tid & 3;    // column block: cols [16*tx, 16*tx+16)
    const int ty = tid >> 2;   // node within tile (0..31)

    unsigned long long acc[8];
#pragma unroll
    for (int p = 0; p < 8; p++) acc[p] = 0ull;

    const ulonglong2* WsU2 = (const ulonglong2*)Ws;  // 16 ulonglong2 per k-row
    const float* row = inS + ty * STR;

#pragma unroll 8
    for (int k = 0; k < K; k++) {
        float r = row[k];
        unsigned long long rr;
        asm("mov.b64 %0, {%1, %1};" : "=l"(rr) : "f"(r));
#pragma unroll
        for (int j = 0; j < 4; j++) {
            ulonglong2 w = WsU2[k * 16 + tx * 4 + j];
            acc[2 * j]     = fma2(w.x, rr, acc[2 * j]);
            acc[2 * j + 1] = fma2(w.y, rr, acc[2 * j + 1]);
        }
    }

    int node = base + ty;
    if (node < n) {
        ulonglong2* o = (ulonglong2*)(out + (size_t)node * 64 + tx * 16);
#pragma unroll
        for (int j = 0; j < 4; j++) o[j] = make_ulonglong2(acc[2 * j], acc[2 * j + 1]);
    }
}

// ---------------- agg init: self-loop + bias ----------------
// agg[i][c] = t[i][c] * dis[i]^2 + b[c]
__global__ void init_agg_kernel(const float* __restrict__ b, int n) {
    int i = blockIdx.x * blockDim.x + threadIdx.x;  // over n*16 float4s
    if (i < n * 16) {
        int node = i >> 4;
        int c4 = i & 15;
        float s = g_dis[node]; s = s * s;
        float4 v = ((const float4*)g_t)[i];
        float4 bb = ((const float4*)b)[c4];
        float4 r;
        r.x = v.x * s + bb.x; r.y = v.y * s + bb.y;
        r.z = v.z * s + bb.z; r.w = v.w * s + bb.w;
        ((float4*)g_agg)[i] = r;
    }
}

// ---------------- edge scatter: agg[dst] += t[src] * norm ----------------
// 16 lanes per edge, float4 vector reductions (contiguous 256B per edge).
__global__ void scatter_kernel(const int* __restrict__ src,
                               const int* __restrict__ dst, int E) {
    int t = blockIdx.x * blockDim.x + threadIdx.x;
    int e = t >> 4;
    int l = t & 15;
    if (e < E) {
        int s = src[e];
        int d = dst[e];
        float nm = g_norm[e];
        float4 v = ((const float4*)(g_t + (size_t)s * HID))[l];
        float* p = g_agg + (size_t)d * HID + l * 4;
        asm volatile("red.global.add.v4.f32 [%0], {%1, %2, %3, %4};"
                     :: "l"(p), "f"(v.x * nm), "f"(v.y * nm),
                        "f"(v.z * nm), "f"(v.w * nm)
                     : "memory");
    }
}

// ---------------- pooling + output linear ----------------
// batch_index is sorted: block g binary-searches its node range. relu of the
// last layer is fused here. Output linear fused into the block reduction.
__global__ void pool_out_kernel(const int* __restrict__ batch,
                                const float* __restrict__ Wout,
                                const float* __restrict__ bout,
                                float* __restrict__ out,
                                float* __restrict__ pooled, int n) {
    int g = blockIdx.x;
    int c = threadIdx.x;  // 64 threads, one per hidden channel

    // lower_bound(batch, g)
    int a = 0, b = n;
    while (a < b) { int m = (a + b) >> 1; if (batch[m] < g) a = m + 1; else b = m; }
    int start = a;
    // upper_bound(batch, g)
    b = n;
    while (a < b) { int m = (a + b) >> 1; if (batch[m] <= g) a = m + 1; else b = m; }
    int end = a;

    float sum = 0.f, mx = 0.f;
#pragma unroll 4
    for (int i = start; i < end; i++) {
        float v = fmaxf(g_agg[(size_t)i * 64 + c], 0.f);
        sum += v;
        mx = fmaxf(mx, v);
    }
    int cnt = end - start;
    float mean = (cnt > 0) ? sum / (float)cnt : 0.f;  // cnt==0 -> mean 0, mx 0

    pooled[(size_t)g * 128 + c] = mean;
    pooled[(size_t)g * 128 + 64 + c] = mx;

    float partial = mean * Wout[c] + mx * Wout[64 + c];
#pragma unroll
    for (int o = 16; o > 0; o >>= 1)
        partial += __shfl_down_sync(0xffffffffu, partial, o);
    __shared__ float ws[2];
    if ((threadIdx.x & 31) == 0) ws[threadIdx.x >> 5] = partial;
    __syncthreads();
    if (threadIdx.x == 0) out[g] = ws[0] + ws[1] + bout[0];
}

// ---------------- host ----------------
extern "C" void kernel_launch(void* const* d_in, const int* in_sizes, int n_in,
                              void* d_out, int out_size) {
    const float* x     = (const float*)d_in[0];
    const int*   edge  = (const int*)d_in[1];     // int64 inputs arrive as int32
    const int*   batch = (const int*)d_in[2];
    const float* W1 = (const float*)d_in[3];  const float* b1 = (const float*)d_in[4];
    const float* W2 = (const float*)d_in[5];  const float* b2 = (const float*)d_in[6];
    const float* W3 = (const float*)d_in[7];  const float* b3 = (const float*)d_in[8];
    const float* W4 = (const float*)d_in[9];  const float* b4 = (const float*)d_in[10];
    const float* Wout = (const float*)d_in[11]; const float* bout = (const float*)d_in[12];

    int N = in_sizes[0] / 128;
    int E = in_sizes[1] / 2;
    int G = out_size / 129;  // out[G,1] + pooled[G,128]

    const int* src = edge;
    const int* dst = edge + E;

    float* out_p    = (float*)d_out;
    float* pooled_p = out_p + G;

    float *tptr = nullptr, *aptr = nullptr;
    cudaGetSymbolAddress((void**)&tptr, g_t);
    cudaGetSymbolAddress((void**)&aptr, g_agg);

    const int smem128 = (128 * 64 + 32 * (128 + 4)) * (int)sizeof(float);  // 49664B
    const int smem64  = (64 * 64 + 32 * (64 + 4)) * (int)sizeof(float);
    cudaFuncSetAttribute(gemm64_kernel<128, false>,
                         cudaFuncAttributeMaxDynamicSharedMemorySize, smem128);
    cudaFuncSetAttribute(gemm64_kernel<64, true>,
                         cudaFuncAttributeMaxDynamicSharedMemorySize, smem64);

    // degree / normalization
    zero_deg_kernel<<<(N + 255) / 256, 256>>>(N);
    count_deg_kernel<<<(E + 255) / 256, 256>>>(dst, E);
    compute_dis_kernel<<<(N + 255) / 256, 256>>>(N);
    compute_norm_kernel<<<(E + 255) / 256, 256>>>(src, dst, E);

    int gblocks   = (N + 31) / 32;
    int ia_blocks = (N * 16 + 255) / 256;
    long long sthreads = (long long)E * 16;
    int s_blocks = (int)((sthreads + 255) / 256);

    // layer 1: in = x (K=128, no relu on input)
    gemm64_kernel<128, false><<<gblocks, 128, smem128>>>(x, W1, tptr, N);
    init_agg_kernel<<<ia_blocks, 256>>>(b1, N);
    scatter_kernel<<<s_blocks, 256>>>(src, dst, E);
    // layers 2..4: in = relu(agg)
    gemm64_kernel<64, true><<<gblocks, 128, smem64>>>(aptr, W2, tptr, N);
    init_agg_kernel<<<ia_blocks, 256>>>(b2, N);
    scatter_kernel<<<s_blocks, 256>>>(src, dst, E);

    gemm64_kernel<64, true><<<gblocks, 128, smem64>>>(aptr, W3, tptr, N);
    init_agg_kernel<<<ia_blocks, 256>>>(b3, N);
    scatter_kernel<<<s_blocks, 256>>>(src, dst, E);

    gemm64_kernel<64, true><<<gblocks, 128, smem64>>>(aptr, W4, tptr, N);
    init_agg_kernel<<<ia_blocks, 256>>>(b4, N);
    scatter_kernel<<<s_blocks, 256>>>(src, dst, E);

    // pooling (+ fused output linear), relu of layer 4 fused in
    pool_out_kernel<<<G, 64>>>(batch, Wout, bout, out_p, pooled_p, N);
}

// round 3
// speedup vs baseline: 1.2462x; 1.2462x over previous
#include <cuda_runtime.h>

#define MAXN 100000
#define MAXE 1600000
#define HID 64
#define SCAN_BLK 1024   // elements per scan block
#define MAX_SCAN_BLOCKS 256

// ---- scratch (device globals; no allocation allowed) ----
__device__ __align__(256) float g_t[MAXN * HID];      // h @ W
__device__ __align__(256) float g_agg[MAXN * HID];    // aggregated messages
__device__ __align__(256) float g_dis[MAXN];          // deg^{-1/2}
__device__ __align__(256) int   g_deg[MAXN];
__device__ __align__(256) int   g_rowptr[MAXN + 1];   // CSR row pointers (by dst)
__device__ __align__(256) int   g_cursor[MAXN];       // binning cursors
__device__ __align__(256) int   g_blocksum[MAX_SCAN_BLOCKS];
__device__ __align__(256) int   g_blockoff[MAX_SCAN_BLOCKS];
__device__ __align__(256) int   g_csrc[MAXE];         // CSR: src node per slot
__device__ __align__(256) float g_cnorm[MAXE];        // CSR: edge norm per slot

// ---------------- prep ----------------
__global__ void zero_deg_kernel(int n) {
    int i = blockIdx.x * blockDim.x + threadIdx.x;
    if (i < n) g_deg[i] = 0;
}

__global__ void count_deg_kernel(const int* __restrict__ dst, int E) {
    int e = blockIdx.x * blockDim.x + threadIdx.x;
    if (e < E) atomicAdd(&g_deg[dst[e]], 1);
}

__global__ void compute_dis_kernel(int n) {
    int i = blockIdx.x * blockDim.x + threadIdx.x;
    if (i < n) g_dis[i] = rsqrtf((float)(g_deg[i] + 1));  // +1 self loop
}

// ---- exclusive scan of g_deg -> g_rowptr (3 kernels) ----
__global__ void scan_part_kernel(int n) {
    __shared__ int sm[256];
    int tid = threadIdx.x;
    int base = blockIdx.x * SCAN_BLK + tid * 4;
    int v[4];
#pragma unroll
    for (int j = 0; j < 4; j++) v[j] = (base + j < n) ? g_deg[base + j] : 0;
    int tsum = v[0] + v[1] + v[2] + v[3];
    sm[tid] = tsum;
    __syncthreads();
    // Hillis-Steele inclusive scan
#pragma unroll
    for (int off = 1; off < 256; off <<= 1) {
        int t2 = (tid >= off) ? sm[tid - off] : 0;
        __syncthreads();
        sm[tid] += t2;
        __syncthreads();
    }
    if (tid == 255) g_blocksum[blockIdx.x] = sm[255];
    int run = sm[tid] - tsum;  // exclusive
#pragma unroll
    for (int j = 0; j < 4; j++) {
        if (base + j < n) g_rowptr[base + j] = run;
        run += v[j];
    }
}

__global__ void scan_top_kernel(int nb) {
    __shared__ int sm[256];
    int tid = threadIdx.x;
    int v = (tid < nb) ? g_blocksum[tid] : 0;
    sm[tid] = v;
    __syncthreads();
#pragma unroll
    for (int off = 1; off < 256; off <<= 1) {
        int t2 = (tid >= off) ? sm[tid - off] : 0;
        __syncthreads();
        sm[tid] += t2;
        __syncthreads();
    }
    if (tid < nb) g_blockoff[tid] = sm[tid] - v;  // exclusive
}

__global__ void scan_add_kernel(int n, int E) {
    int i = blockIdx.x * blockDim.x + threadIdx.x;
    if (i < n) {
        g_rowptr[i] += g_blockoff[i / SCAN_BLK];
        g_cursor[i] = 0;
    } else if (i == n) {
        g_rowptr[n] = E;
    }
}

// ---- bin edges into CSR slots, fusing norm computation ----
__global__ void permute_kernel(const int* __restrict__ src,
                               const int* __restrict__ dst, int E) {
    int e = blockIdx.x * blockDim.x + threadIdx.x;
    if (e < E) {
        int s = src[e];
        int d = dst[e];
        int pos = atomicAdd(&g_cursor[d], 1);
        int slot = g_rowptr[d] + pos;
        g_csrc[slot] = s;
        g_cnorm[slot] = g_dis[s] * g_dis[d];
    }
}

// ---------------- GEMM: out[N,64] = f(in)[N,K] @ W[K,64] ----------------
__device__ __forceinline__ unsigned long long fma2(unsigned long long a,
                                                   unsigned long long b,
                                                   unsigned long long c) {
    unsigned long long d;
    asm("fma.rn.f32x2 %0, %1, %2, %3;" : "=l"(d) : "l"(a), "l"(b), "l"(c));
    return d;
}

template <int K, bool RELU>
__global__ void gemm64_kernel(const float* __restrict__ in,
                              const float* __restrict__ W,
                              float* __restrict__ out, int n) {
    extern __shared__ float sm[];
    float* Ws  = sm;                // K*64 floats
    float* inS = sm + K * 64;       // 32 rows, stride K+4
    const int tid = threadIdx.x;    // 128 threads
    const int STR = K + 4;

    {
        const float4* W4 = (const float4*)W;
        float4* Ws4 = (float4*)Ws;
        for (int i = tid; i < K * 16; i += 128) Ws4[i] = W4[i];
    }
    int base = blockIdx.x * 32;
    {
        const int K4 = K / 4;
        const float4* in4 = (const float4*)(in + (size_t)base * K);
        for (int i = tid; i < 32 * K4; i += 128) {
            int node = i / K4, k4 = i % K4;
            float4 v;
            if (base + node < n) v = in4[i];
            else v = make_float4(0.f, 0.f, 0.f, 0.f);
            if (RELU) {
                v.x = fmaxf(v.x, 0.f); v.y = fmaxf(v.y, 0.f);
                v.z = fmaxf(v.z, 0.f); v.w = fmaxf(v.w, 0.f);
            }
            ((float4*)(inS + node * STR))[k4] = v;
        }
    }
    __syncthreads();

    const int tx = tid & 3;
    const int ty = tid >> 2;

    unsigned long long acc[8];
#pragma unroll
    for (int p = 0; p < 8; p++) acc[p] = 0ull;

    const ulonglong2* WsU2 = (const ulonglong2*)Ws;
    const float* row = inS + ty * STR;

#pragma unroll 8
    for (int k = 0; k < K; k++) {
        float r = row[k];
        unsigned long long rr;
        asm("mov.b64 %0, {%1, %1};" : "=l"(rr) : "f"(r));
#pragma unroll
        for (int j = 0; j < 4; j++) {
            ulonglong2 w = WsU2[k * 16 + tx * 4 + j];
            acc[2 * j]     = fma2(w.x, rr, acc[2 * j]);
            acc[2 * j + 1] = fma2(w.y, rr, acc[2 * j + 1]);
        }
    }

    int node = base + ty;
    if (node < n) {
        ulonglong2* o = (ulonglong2*)(out + (size_t)node * 64 + tx * 16);
#pragma unroll
        for (int j = 0; j < 4; j++) o[j] = make_ulonglong2(acc[2 * j], acc[2 * j + 1]);
    }
}

// ---------------- CSR gather: agg[i] = sum_{e in(i)} t[src_e]*norm_e
//                              + t[i]*dis_i^2 + b ----------------
// 16 lanes per node, float4 accumulator (64 channels). One coalesced write.
__global__ void gather_kernel(const float* __restrict__ b, int n) {
    int node = blockIdx.x * 16 + (threadIdx.x >> 4);  // 256 thr = 16 nodes
    int l = threadIdx.x & 15;
    if (node >= n) return;

    int e  = g_rowptr[node];
    int e1 = g_rowptr[node + 1];

    float4 acc = make_float4(0.f, 0.f, 0.f, 0.f);

    for (; e + 1 < e1; e += 2) {
        int a0 = g_csrc[e];
        int a1 = g_csrc[e + 1];
        float n0 = g_cnorm[e];
        float n1 = g_cnorm[e + 1];
        float4 v0 = *(const float4*)(g_t + (size_t)a0 * HID + l * 4);
        float4 v1 = *(const float4*)(g_t + (size_t)a1 * HID + l * 4);
        acc.x += v0.x * n0; acc.y += v0.y * n0;
        acc.z += v0.z * n0; acc.w += v0.w * n0;
        acc.x += v1.x * n1; acc.y += v1.y * n1;
        acc.z += v1.z * n1; acc.w += v1.w * n1;
    }
    if (e < e1) {
        int a0 = g_csrc[e];
        float n0 = g_cnorm[e];
        float4 v0 = *(const float4*)(g_t + (size_t)a0 * HID + l * 4);
        acc.x += v0.x * n0; acc.y += v0.y * n0;
        acc.z += v0.z * n0; acc.w += v0.w * n0;
    }

    // self-loop + bias
    float s = g_dis[node]; s = s * s;
    float4 v = *(const float4*)(g_t + (size_t)node * HID + l * 4);
    float4 bb = ((const float4*)b)[l];
    acc.x = fmaf(v.x, s, acc.x) + bb.x;
    acc.y = fmaf(v.y, s, acc.y) + bb.y;
    acc.z = fmaf(v.z, s, acc.z) + bb.z;
    acc.w = fmaf(v.w, s, acc.w) + bb.w;

    *(float4*)(g_agg + (size_t)node * HID + l * 4) = acc;
}

// ---------------- pooling + output linear ----------------
__global__ void pool_out_kernel(const int* __restrict__ batch,
                                const float* __restrict__ Wout,
                                const float* __restrict__ bout,
                                float* __restrict__ out,
                                float* __restrict__ pooled, int n) {
    int g = blockIdx.x;
    int c = threadIdx.x;  // 64 threads

    int a = 0, b = n;
    while (a < b) { int m = (a + b) >> 1; if (batch[m] < g) a = m + 1; else b = m; }
    int start = a;
    b = n;
    while (a < b) { int m = (a + b) >> 1; if (batch[m] <= g) a = m + 1; else b = m; }
    int end = a;

    float sum = 0.f, mx = 0.f;
#pragma unroll 4
    for (int i = start; i < end; i++) {
        float v = fmaxf(g_agg[(size_t)i * 64 + c], 0.f);
        sum += v;
        mx = fmaxf(mx, v);
    }
    int cnt = end - start;
    float mean = (cnt > 0) ? sum / (float)cnt : 0.f;

    pooled[(size_t)g * 128 + c] = mean;
    pooled[(size_t)g * 128 + 64 + c] = mx;

    float partial = mean * Wout[c] + mx * Wout[64 + c];
#pragma unroll
    for (int o = 16; o > 0; o >>= 1)
        partial += __shfl_down_sync(0xffffffffu, partial, o);
    __shared__ float ws[2];
    if ((threadIdx.x & 31) == 0) ws[threadIdx.x >> 5] = partial;
    __syncthreads();
    if (threadIdx.x == 0) out[g] = ws[0] + ws[1] + bout[0];
}

// ---------------- host ----------------
extern "C" void kernel_launch(void* const* d_in, const int* in_sizes, int n_in,
                              void* d_out, int out_size) {
    const float* x     = (const float*)d_in[0];
    const int*   edge  = (const int*)d_in[1];     // int64 inputs arrive as int32
    const int*   batch = (const int*)d_in[2];
    const float* W1 = (const float*)d_in[3];  const float* b1 = (const float*)d_in[4];
    const float* W2 = (const float*)d_in[5];  const float* b2 = (const float*)d_in[6];
    const float* W3 = (const float*)d_in[7];  const float* b3 = (const float*)d_in[8];
    const float* W4 = (const float*)d_in[9];  const float* b4 = (const float*)d_in[10];
    const float* Wout = (const float*)d_in[11]; const float* bout = (const float*)d_in[12];

    int N = in_sizes[0] / 128;
    int E = in_sizes[1] / 2;
    int G = out_size / 129;  // out[G,1] + pooled[G,128]

    const int* src = edge;
    const int* dst = edge + E;

    float* out_p    = (float*)d_out;
    float* pooled_p = out_p + G;

    float *tptr = nullptr, *aptr = nullptr;
    cudaGetSymbolAddress((void**)&tptr, g_t);
    cudaGetSymbolAddress((void**)&aptr, g_agg);

    const int smem128 = (128 * 64 + 32 * (128 + 4)) * (int)sizeof(float);
    const int smem64  = (64 * 64 + 32 * (64 + 4)) * (int)sizeof(float);
    cudaFuncSetAttribute(gemm64_kernel<128, false>,
                         cudaFuncAttributeMaxDynamicSharedMemorySize, smem128);
    cudaFuncSetAttribute(gemm64_kernel<64, true>,
                         cudaFuncAttributeMaxDynamicSharedMemorySize, smem64);

    // ---- degree + CSR build ----
    zero_deg_kernel<<<(N + 255) / 256, 256>>>(N);
    count_deg_kernel<<<(E + 255) / 256, 256>>>(dst, E);
    compute_dis_kernel<<<(N + 255) / 256, 256>>>(N);

    int nsb = (N + SCAN_BLK - 1) / SCAN_BLK;       // <= 98 for N=100K
    scan_part_kernel<<<nsb, 256>>>(N);
    scan_top_kernel<<<1, 256>>>(nsb);
    scan_add_kernel<<<(N + 256) / 256, 256>>>(N, E);
    permute_kernel<<<(E + 255) / 256, 256>>>(src, dst, E);

    int gblocks = (N + 31) / 32;
    int agblocks = (N + 15) / 16;

    // layer 1
    gemm64_kernel<128, false><<<gblocks, 128, smem128>>>(x, W1, tptr, N);
    gather_kernel<<<agblocks, 256>>>(b1, N);
    // layers 2..4
    gemm64_kernel<64, true><<<gblocks, 128, smem64>>>(aptr, W2, tptr, N);
    gather_kernel<<<agblocks, 256>>>(b2, N);

    gemm64_kernel<64, true><<<gblocks, 128, smem64>>>(aptr, W3, tptr, N);
    gather_kernel<<<agblocks, 256>>>(b3, N);

    gemm64_kernel<64, true><<<gblocks, 128, smem64>>>(aptr, W4, tptr, N);
    gather_kernel<<<agblocks, 256>>>(b4, N);

    // pooling (+ fused output linear), relu of layer 4 fused in
    pool_out_kernel<<<G, 64>>>(batch, Wout, bout, out_p, pooled_p, N);
}